// round 1
// baseline (speedup 1.0000x reference)
#include <cuda_runtime.h>

// LIF membrane update:
//   v_new[b,n] = ALPHA*v[b,n] + sum_i x[b,i,n]*w[i,n] - V_TH*z[b,n]
//   z_new[b,n] = (v_new[b,n] - V_TH > 0) ? 1 : 0
// Shapes: x[128,1024,512], w[1024,512], v[128,512], z[128,512]
// Pure HBM-bound streaming reduction (x = 256 MB read once).

#define B_    128
#define N_IN_ 1024
#define NN_   512
#define NN4_  (NN_ / 4)        // 128 float4 per row
#define ALPHA_ 0.995f
#define V_TH_  2.0f

#define ISLICES 8
#define IPER    (N_IN_ / ISLICES)   // 128 i per slice
#define NTILE4  32                  // 32 float4 = 128 n per block
#define THREADS (ISLICES * NTILE4)  // 256

__global__ __launch_bounds__(THREADS)
void lif_kernel(const float4* __restrict__ x,
                const float4* __restrict__ w,
                const float4* __restrict__ v,
                const float4* __restrict__ z,
                float4* __restrict__ out)
{
    __shared__ float4 smem[THREADS];

    const int b     = blockIdx.x >> 2;       // 4 n-tiles per batch row
    const int ntile = blockIdx.x & 3;
    const int lane  = threadIdx.x & 31;
    const int slice = threadIdx.x >> 5;
    const int n4    = ntile * NTILE4 + lane; // 0..127 (float4 index in n)

    const float4* xb = x + (size_t)b * N_IN_ * NN4_ + n4;
    const float4* wb = w + n4;

    float4 acc = make_float4(0.f, 0.f, 0.f, 0.f);
    const int i0 = slice * IPER;

    #pragma unroll 4
    for (int i = i0; i < i0 + IPER; ++i) {
        float4 xv = __ldcs(&xb[(size_t)i * NN4_]);  // streaming: no L2 pollution
        float4 wv = __ldg (&wb[(size_t)i * NN4_]);  // L2-resident, reused 128x
        acc.x += xv.x * wv.x;
        acc.y += xv.y * wv.y;
        acc.z += xv.z * wv.z;
        acc.w += xv.w * wv.w;
    }

    smem[threadIdx.x] = acc;
    __syncthreads();

    if (threadIdx.x < NTILE4) {
        float4 sum = smem[threadIdx.x];
        #pragma unroll
        for (int k = 1; k < ISLICES; ++k) {
            float4 t = smem[threadIdx.x + NTILE4 * k];
            sum.x += t.x; sum.y += t.y; sum.z += t.z; sum.w += t.w;
        }

        const int on = b * NN4_ + n4;   // output float4 index
        float4 vv = v[on];
        float4 zz = z[on];

        float4 vn;
        vn.x = ALPHA_ * vv.x + sum.x - V_TH_ * zz.x;
        vn.y = ALPHA_ * vv.y + sum.y - V_TH_ * zz.y;
        vn.z = ALPHA_ * vv.z + sum.z - V_TH_ * zz.z;
        vn.w = ALPHA_ * vv.w + sum.w - V_TH_ * zz.w;

        float4 zn;
        zn.x = (vn.x - V_TH_ > 0.f) ? 1.f : 0.f;
        zn.y = (vn.y - V_TH_ > 0.f) ? 1.f : 0.f;
        zn.z = (vn.z - V_TH_ > 0.f) ? 1.f : 0.f;
        zn.w = (vn.w - V_TH_ > 0.f) ? 1.f : 0.f;

        out[on] = vn;                         // v_new: first B*NN floats
        out[(B_ * NN4_) + on] = zn;           // z_new: next  B*NN floats
    }
}

extern "C" void kernel_launch(void* const* d_in, const int* in_sizes, int n_in,
                              void* d_out, int out_size)
{
    const float4* x = (const float4*)d_in[0];  // [128,1024,512] f32
    const float4* w = (const float4*)d_in[1];  // [1024,512]     f32
    const float4* v = (const float4*)d_in[2];  // [128,512]      f32
    const float4* z = (const float4*)d_in[3];  // [128,512]      f32
    float4* out = (float4*)d_out;              // [2,128,512]    f32 (v_new ++ z_new)

    (void)in_sizes; (void)n_in; (void)out_size;

    dim3 grid(B_ * (NN_ / 128));  // 512 blocks
    lif_kernel<<<grid, THREADS>>>(x, w, v, z, out);
}